// round 2
// baseline (speedup 1.0000x reference)
#include <cuda_runtime.h>
#include <math.h>

// Problem-fixed maxima (setup_inputs: N=50000, E=1600000, +N self loops)
#define MAXN 50048
#define MAXE 1650048

// ------------ static device scratch (no allocations allowed) -------------
__device__ float d_h1[MAXN * 64];    // layer1 projected features [N,64]
__device__ float d_as1[MAXN * 8];    // layer1 a_src  [N,8]
__device__ float d_ad1[MAXN * 8];    // layer1 a_dst  [N,8]
__device__ float d_x1[MAXN * 64];    // layer1 output after bias+ELU [N,64]
__device__ float d_h2[MAXN * 128];   // layer2 projected features [N,128]
__device__ float d_as2[MAXN];        // layer2 a_src [N]
__device__ float d_ad2[MAXN];        // layer2 a_dst [N]
__device__ int   d_deg[MAXN];
__device__ int   d_off[MAXN + 1];
__device__ int   d_cur[MAXN];
__device__ int   d_ssrc[MAXE];       // src node ids sorted by dst (CSR)

// ---------------------------- CSR build ----------------------------------
__global__ void k_zero_deg(int n) {
    int i = blockIdx.x * blockDim.x + threadIdx.x;
    if (i < n) d_deg[i] = 0;
}

__global__ void k_hist(const int* __restrict__ ei, int E, int ET) {
    int e = blockIdx.x * blockDim.x + threadIdx.x;
    if (e >= ET) return;
    int dst = (e < E) ? ei[E + e] : (e - E);
    atomicAdd(&d_deg[dst], 1);
}

// single-block exclusive scan of deg -> off (and cursor copy)
__global__ void k_scan(int n) {
    __shared__ int sh[1024];
    int t = threadIdx.x;
    int carry = 0;
    for (int base = 0; base < n; base += 1024) {
        int v = (base + t < n) ? d_deg[base + t] : 0;
        sh[t] = v;
        __syncthreads();
        for (int o = 1; o < 1024; o <<= 1) {
            int x = (t >= o) ? sh[t - o] : 0;
            __syncthreads();
            sh[t] += x;
            __syncthreads();
        }
        int incl = sh[t];
        if (base + t < n) {
            int ex = carry + incl - v;
            d_off[base + t] = ex;
            d_cur[base + t] = ex;
        }
        carry += sh[1023];
        __syncthreads();
    }
    if (t == 0) d_off[n] = carry;
}

__global__ void k_scatter(const int* __restrict__ ei, int E, int ET) {
    int e = blockIdx.x * blockDim.x + threadIdx.x;
    if (e >= ET) return;
    int src, dst;
    if (e < E) { src = ei[e]; dst = ei[E + e]; }
    else       { src = e - E; dst = e - E; }
    int pos = atomicAdd(&d_cur[dst], 1);
    d_ssrc[pos] = src;
}

// ---------------------------- Layer 1 GEMM -------------------------------
// h1 = x[N,128] @ W1[128,64]; also a_src1/a_dst1 = (h1.reshape(N,8,8)*att).sum(-1)
__global__ __launch_bounds__(256) void k_gemm1(
    const float* __restrict__ x, const float* __restrict__ W1,
    const float* __restrict__ as, const float* __restrict__ ad, int n)
{
    __shared__ float Ws[128 * 64];
    __shared__ float atts[64], attd[64];
    __shared__ float xs[8][128];
    int t = threadIdx.x, w = t >> 5, l = t & 31;
    for (int i = t; i < 8192; i += 256) Ws[i] = W1[i];
    if (t < 64) { atts[t] = as[t]; attd[t] = ad[t]; }
    __syncthreads();
    const float2* Wp = (const float2*)Ws;
    for (int row = blockIdx.x * 8 + w; row < n; row += gridDim.x * 8) {
        float4 xv = ((const float4*)(x + (size_t)row * 128))[l];
        xs[w][l * 4 + 0] = xv.x; xs[w][l * 4 + 1] = xv.y;
        xs[w][l * 4 + 2] = xv.z; xs[w][l * 4 + 3] = xv.w;
        __syncwarp();
        float a0 = 0.f, a1 = 0.f;
#pragma unroll 16
        for (int k = 0; k < 128; k++) {
            float xk = xs[w][k];
            float2 wv = Wp[k * 32 + l];
            a0 += xk * wv.x;
            a1 += xk * wv.y;
        }
        ((float2*)(d_h1 + (size_t)row * 64))[l] = make_float2(a0, a1);
        float ps = a0 * atts[2 * l] + a1 * atts[2 * l + 1];
        float pd = a0 * attd[2 * l] + a1 * attd[2 * l + 1];
        ps += __shfl_xor_sync(0xffffffffu, ps, 1);
        ps += __shfl_xor_sync(0xffffffffu, ps, 2);
        pd += __shfl_xor_sync(0xffffffffu, pd, 1);
        pd += __shfl_xor_sync(0xffffffffu, pd, 2);
        if ((l & 3) == 0) {
            d_as1[row * 8 + (l >> 2)] = ps;
            d_ad1[row * 8 + (l >> 2)] = pd;
        }
        __syncwarp();
    }
}

// --------------------------- Layer 1 aggregate ---------------------------
// warp per dst node; lane l owns channels 2l,2l+1 (head = l>>2)
__global__ __launch_bounds__(256) void k_agg1(const float* __restrict__ bias1, int n) {
    int t = threadIdx.x, w = t >> 5, l = t & 31;
    int node = blockIdx.x * 8 + w;
    if (node >= n) return;
    int hl = l >> 2;                         // head for accumulation lanes
    float adv = d_ad1[node * 8 + (l & 7)];   // a_dst for alpha-compute role (head l&7)
    int beg = d_off[node], end = d_off[node + 1];
    float acc0 = 0.f, acc1 = 0.f, dsum = 0.f;
    for (int ch = beg; ch < end; ch += 32) {
        int gi = ch + l;
        int idx = (gi < end) ? d_ssrc[gi] : -1;
        int cnt = min(32, end - ch);
        for (int j4 = 0; j4 < 8; j4++) {
            if (j4 * 4 >= cnt) break;
            int ka = j4 * 4 + (l >> 3);      // which edge this lane computes alpha for
            int sA = __shfl_sync(0xffffffffu, idx, j4 * 4 + (l >> 3));
            float e = 0.f;
            if (ka < cnt) {
                float al = d_as1[sA * 8 + (l & 7)] + adv;
                al = (al >= 0.f) ? al : 0.2f * al;
                e = __expf(al);
            }
#pragma unroll
            for (int j = 0; j < 4; j++) {
                if (j4 * 4 + j >= cnt) break;
                int s = __shfl_sync(0xffffffffu, idx, j4 * 4 + j);
                float ev = __shfl_sync(0xffffffffu, e, j * 8 + hl);
                float2 hv = ((const float2*)(d_h1 + (size_t)s * 64))[l];
                acc0 += ev * hv.x;
                acc1 += ev * hv.y;
                dsum += ev;
            }
        }
    }
    float inv = 1.f / (dsum + 1e-16f);
    float o0 = acc0 * inv + bias1[2 * l];
    float o1 = acc1 * inv + bias1[2 * l + 1];
    o0 = (o0 > 0.f) ? o0 : expm1f(o0);
    o1 = (o1 > 0.f) ? o1 : expm1f(o1);
    ((float2*)(d_x1 + (size_t)node * 64))[l] = make_float2(o0, o1);
}

// ---------------------------- Layer 2 GEMM -------------------------------
// h2 = x1[N,64] @ W2[64,128]; a_src2/a_dst2 = h2 . att2
__global__ __launch_bounds__(256) void k_gemm2(
    const float* __restrict__ W2, const float* __restrict__ as2,
    const float* __restrict__ ad2, int n)
{
    __shared__ float Ws[64 * 128];
    __shared__ float atts[128], attd[128];
    __shared__ float xs[8][64];
    int t = threadIdx.x, w = t >> 5, l = t & 31;
    for (int i = t; i < 8192; i += 256) Ws[i] = W2[i];
    if (t < 128) { atts[t] = as2[t]; attd[t] = ad2[t]; }
    __syncthreads();
    const float4* Wp = (const float4*)Ws;
    for (int row = blockIdx.x * 8 + w; row < n; row += gridDim.x * 8) {
        float2 xv = ((const float2*)(d_x1 + (size_t)row * 64))[l];
        xs[w][2 * l] = xv.x; xs[w][2 * l + 1] = xv.y;
        __syncwarp();
        float c0 = 0.f, c1 = 0.f, c2 = 0.f, c3 = 0.f;
#pragma unroll 16
        for (int k = 0; k < 64; k++) {
            float xk = xs[w][k];
            float4 wv = Wp[k * 32 + l];
            c0 += xk * wv.x; c1 += xk * wv.y;
            c2 += xk * wv.z; c3 += xk * wv.w;
        }
        ((float4*)(d_h2 + (size_t)row * 128))[l] = make_float4(c0, c1, c2, c3);
        float ps = c0 * atts[4 * l] + c1 * atts[4 * l + 1] + c2 * atts[4 * l + 2] + c3 * atts[4 * l + 3];
        float pd = c0 * attd[4 * l] + c1 * attd[4 * l + 1] + c2 * attd[4 * l + 2] + c3 * attd[4 * l + 3];
#pragma unroll
        for (int o = 16; o; o >>= 1) {
            ps += __shfl_xor_sync(0xffffffffu, ps, o);
            pd += __shfl_xor_sync(0xffffffffu, pd, o);
        }
        if (l == 0) { d_as2[row] = ps; d_ad2[row] = pd; }
        __syncwarp();
    }
}

// --------------------------- Layer 2 aggregate ---------------------------
// warp per dst node; lane l owns channels 4l..4l+3; H=1 -> scalar alpha
__global__ __launch_bounds__(256) void k_agg2(
    const float* __restrict__ bias2, float* __restrict__ out, int n)
{
    int t = threadIdx.x, w = t >> 5, l = t & 31;
    int node = blockIdx.x * 8 + w;
    if (node >= n) return;
    float adv = d_ad2[node];
    int beg = d_off[node], end = d_off[node + 1];
    float c0 = 0.f, c1 = 0.f, c2 = 0.f, c3 = 0.f;
    float dpart = 0.f;
    for (int ch = beg; ch < end; ch += 32) {
        int gi = ch + l;
        int idx = -1;
        float e = 0.f;
        if (gi < end) {
            idx = d_ssrc[gi];
            float al = d_as2[idx] + adv;
            al = (al >= 0.f) ? al : 0.2f * al;
            e = __expf(al);
            dpart += e;
        }
        int cnt = min(32, end - ch);
        for (int j = 0; j < cnt; j++) {
            int s = __shfl_sync(0xffffffffu, idx, j);
            float ev = __shfl_sync(0xffffffffu, e, j);
            float4 hv = ((const float4*)(d_h2 + (size_t)s * 128))[l];
            c0 += ev * hv.x; c1 += ev * hv.y;
            c2 += ev * hv.z; c3 += ev * hv.w;
        }
    }
#pragma unroll
    for (int o = 16; o; o >>= 1) dpart += __shfl_xor_sync(0xffffffffu, dpart, o);
    float inv = 1.f / (dpart + 1e-16f);
    float4 b = ((const float4*)bias2)[l];
    float4 o4 = make_float4(c0 * inv + b.x, c1 * inv + b.y,
                            c2 * inv + b.z, c3 * inv + b.w);
    ((float4*)(out + (size_t)node * 128))[l] = o4;
}

// ------------------------------- launch ----------------------------------
extern "C" void kernel_launch(void* const* d_in, const int* in_sizes, int n_in,
                              void* d_out, int out_size)
{
    const float* x    = (const float*)d_in[0];
    const int*   ei   = (const int*)d_in[1];     // JAX default: int64 request -> int32
    const float* W1   = (const float*)d_in[2];
    const float* asr1 = (const float*)d_in[3];
    const float* ads1 = (const float*)d_in[4];
    const float* b1   = (const float*)d_in[5];
    const float* W2   = (const float*)d_in[6];
    const float* asr2 = (const float*)d_in[7];
    const float* ads2 = (const float*)d_in[8];
    const float* b2   = (const float*)d_in[9];
    float* out = (float*)d_out;

    int N  = in_sizes[0] / 128;
    int E  = in_sizes[1] / 2;
    int ET = E + N;

    // CSR by destination
    k_zero_deg<<<(N + 255) / 256, 256>>>(N);
    k_hist<<<(ET + 255) / 256, 256>>>(ei, E, ET);
    k_scan<<<1, 1024>>>(N);
    k_scatter<<<(ET + 255) / 256, 256>>>(ei, E, ET);

    // Layer 1
    k_gemm1<<<1250, 256>>>(x, W1, asr1, ads1, N);
    k_agg1<<<(N + 7) / 8, 256>>>(b1, N);

    // Layer 2
    k_gemm2<<<1250, 256>>>(W2, asr2, ads2, N);
    k_agg2<<<(N + 7) / 8, 256>>>(b2, out, N);
}

// round 3
// speedup vs baseline: 1.0409x; 1.0409x over previous
#include <cuda_runtime.h>
#include <math.h>

// Problem-fixed maxima (setup_inputs: N=50000, E=1600000, +N self loops)
#define MAXN 50048
#define MAXE 1650048

// ------------ static device scratch (no allocations allowed) -------------
__device__ float d_h1[MAXN * 64];    // layer1 projected features [N,64]
__device__ float d_as1[MAXN * 8];    // layer1 a_src  [N,8]
__device__ float d_ad1[MAXN * 8];    // layer1 a_dst  [N,8]
__device__ float d_x1[MAXN * 64];    // layer1 output after bias+ELU [N,64]
__device__ float d_h2[MAXN * 128];   // layer2 projected features [N,128]
__device__ float d_as2[MAXN];        // layer2 a_src [N]
__device__ float d_ad2[MAXN];        // layer2 a_dst [N]
__device__ int   d_deg[MAXN];
__device__ int   d_off[MAXN + 1];
__device__ int   d_cur[MAXN];
__device__ int   d_ssrc[MAXE];       // src node ids grouped by dst (CSR)

// ---------------------------- CSR build ----------------------------------
__global__ void k_zero_deg(int n) {
    int i = blockIdx.x * blockDim.x + threadIdx.x;
    if (i < n) d_deg[i] = 0;
}

// histogram of real edges only (self loops handled in scan)
__global__ void k_hist(const int* __restrict__ ei, int E, int vec) {
    int i = blockIdx.x * blockDim.x + threadIdx.x;
    int e = i * 4;
    if (e >= E) return;
    if (vec && e + 3 < E) {
        int4 d = *(const int4*)(ei + E + e);
        atomicAdd(&d_deg[d.x], 1);
        atomicAdd(&d_deg[d.y], 1);
        atomicAdd(&d_deg[d.z], 1);
        atomicAdd(&d_deg[d.w], 1);
    } else {
        for (int j = e; j < E && j < e + 4; j++)
            atomicAdd(&d_deg[ei[E + j]], 1);
    }
}

// single-block 1024-thread warp-shuffle scan; also places self loop as slot 0
// of each segment and initializes cursors past it.
__global__ __launch_bounds__(1024) void k_scan(int n) {
    __shared__ int warpsum[32];
    int t = threadIdx.x, lane = t & 31, wid = t >> 5;
    int ipt = (n + 1023) >> 10;
    int start = t * ipt;
    int endi  = min(start + ipt, n);
    // pass 1: thread-local sum of (deg + 1 self loop)
    int s = 0;
    for (int i = start; i < endi; i++) s += d_deg[i] + 1;
    // warp inclusive scan
    int incl = s;
#pragma unroll
    for (int o = 1; o < 32; o <<= 1) {
        int v = __shfl_up_sync(0xffffffffu, incl, o);
        if (lane >= o) incl += v;
    }
    if (lane == 31) warpsum[wid] = incl;
    __syncthreads();
    if (wid == 0) {
        int v = warpsum[lane];
        int wi = v;
#pragma unroll
        for (int o = 1; o < 32; o <<= 1) {
            int u = __shfl_up_sync(0xffffffffu, wi, o);
            if (lane >= o) wi += u;
        }
        warpsum[lane] = wi - v;  // exclusive
    }
    __syncthreads();
    int run = warpsum[wid] + (incl - s);  // exclusive prefix for this thread
    // pass 2: write offsets, self-loop entry, cursor
    for (int i = start; i < endi; i++) {
        int d = d_deg[i];
        d_off[i]  = run;
        d_ssrc[run] = i;       // self loop occupies slot 0 of the segment
        d_cur[i]  = run + 1;
        run += d + 1;
    }
    if (t == 1023) d_off[n] = run;  // last thread's run == total (E + n)
}

__global__ void k_scatter(const int* __restrict__ ei, int E, int vec) {
    int i = blockIdx.x * blockDim.x + threadIdx.x;
    int e = i * 4;
    if (e >= E) return;
    if (vec && e + 3 < E) {
        int4 s = *(const int4*)(ei + e);
        int4 d = *(const int4*)(ei + E + e);
        d_ssrc[atomicAdd(&d_cur[d.x], 1)] = s.x;
        d_ssrc[atomicAdd(&d_cur[d.y], 1)] = s.y;
        d_ssrc[atomicAdd(&d_cur[d.z], 1)] = s.z;
        d_ssrc[atomicAdd(&d_cur[d.w], 1)] = s.w;
    } else {
        for (int j = e; j < E && j < e + 4; j++)
            d_ssrc[atomicAdd(&d_cur[ei[E + j]], 1)] = ei[j];
    }
}

// ---------------------------- Layer 1 GEMM -------------------------------
// h1 = x[N,128] @ W1[128,64]. x rows live in registers, broadcast via shfl;
// W streamed from shared (1 LDS.64 per k per warp). 4 rows per warp tile.
__global__ __launch_bounds__(256) void k_gemm1(
    const float* __restrict__ x, const float* __restrict__ W1,
    const float* __restrict__ as, const float* __restrict__ ad, int n)
{
    __shared__ float2 Ws[128 * 32];
    __shared__ float atts[64], attd[64];
    int t = threadIdx.x, w = t >> 5, l = t & 31;
    const float2* Wv = (const float2*)W1;
    for (int i = t; i < 4096; i += 256) Ws[i] = Wv[i];
    if (t < 64) { atts[t] = as[t]; attd[t] = ad[t]; }
    __syncthreads();
    int ntiles = (n + 3) >> 2;
    for (int tile = blockIdx.x * 8 + w; tile < ntiles; tile += gridDim.x * 8) {
        int row0 = tile * 4;
        float xr[4][4];
#pragma unroll
        for (int r = 0; r < 4; r++) {
            const float* xp = x + (size_t)min(row0 + r, n - 1) * 128;
#pragma unroll
            for (int c = 0; c < 4; c++) xr[r][c] = xp[l + 32 * c];
        }
        float2 acc[4] = {{0,0},{0,0},{0,0},{0,0}};
#pragma unroll
        for (int c = 0; c < 4; c++) {
#pragma unroll 8
            for (int kk = 0; kk < 32; kk++) {
                float2 wv = Ws[(c * 32 + kk) * 32 + l];
#pragma unroll
                for (int r = 0; r < 4; r++) {
                    float xv = __shfl_sync(0xffffffffu, xr[r][c], kk);
                    acc[r].x += xv * wv.x;
                    acc[r].y += xv * wv.y;
                }
            }
        }
#pragma unroll
        for (int r = 0; r < 4; r++) {
            int row = row0 + r;
            if (row >= n) break;
            ((float2*)(d_h1 + (size_t)row * 64))[l] = acc[r];
            float ps = acc[r].x * atts[2 * l] + acc[r].y * atts[2 * l + 1];
            float pd = acc[r].x * attd[2 * l] + acc[r].y * attd[2 * l + 1];
            ps += __shfl_xor_sync(0xffffffffu, ps, 1);
            ps += __shfl_xor_sync(0xffffffffu, ps, 2);
            pd += __shfl_xor_sync(0xffffffffu, pd, 1);
            pd += __shfl_xor_sync(0xffffffffu, pd, 2);
            if ((l & 3) == 0) {
                d_as1[row * 8 + (l >> 2)] = ps;
                d_ad1[row * 8 + (l >> 2)] = pd;
            }
        }
    }
}

// --------------------------- Layer 1 aggregate ---------------------------
// warp per dst node; lane l owns channels 2l,2l+1 (head = l>>2)
__global__ __launch_bounds__(256) void k_agg1(const float* __restrict__ bias1, int n) {
    int t = threadIdx.x, w = t >> 5, l = t & 31;
    int node = blockIdx.x * 8 + w;
    if (node >= n) return;
    int hl = l >> 2;                         // head for accumulation lanes
    float adv = d_ad1[node * 8 + (l & 7)];   // a_dst for alpha-compute role (head l&7)
    int beg = d_off[node], end = d_off[node + 1];
    float acc0 = 0.f, acc1 = 0.f, dsum = 0.f;
    for (int ch = beg; ch < end; ch += 32) {
        int gi = ch + l;
        int idx = (gi < end) ? d_ssrc[gi] : -1;
        int cnt = min(32, end - ch);
        for (int j4 = 0; j4 < 8; j4++) {
            if (j4 * 4 >= cnt) break;
            int ka = j4 * 4 + (l >> 3);      // which edge this lane computes alpha for
            int sA = __shfl_sync(0xffffffffu, idx, j4 * 4 + (l >> 3));
            float e = 0.f;
            if (ka < cnt) {
                float al = d_as1[sA * 8 + (l & 7)] + adv;
                al = (al >= 0.f) ? al : 0.2f * al;
                e = __expf(al);
            }
#pragma unroll
            for (int j = 0; j < 4; j++) {
                if (j4 * 4 + j >= cnt) break;
                int s = __shfl_sync(0xffffffffu, idx, j4 * 4 + j);
                float ev = __shfl_sync(0xffffffffu, e, j * 8 + hl);
                float2 hv = ((const float2*)(d_h1 + (size_t)s * 64))[l];
                acc0 += ev * hv.x;
                acc1 += ev * hv.y;
                dsum += ev;
            }
        }
    }
    float inv = 1.f / (dsum + 1e-16f);
    float o0 = acc0 * inv + bias1[2 * l];
    float o1 = acc1 * inv + bias1[2 * l + 1];
    o0 = (o0 > 0.f) ? o0 : expm1f(o0);
    o1 = (o1 > 0.f) ? o1 : expm1f(o1);
    ((float2*)(d_x1 + (size_t)node * 64))[l] = make_float2(o0, o1);
}

// ---------------------------- Layer 2 GEMM -------------------------------
// h2 = x1[N,64] @ W2[64,128]; x1 rows in registers + shfl broadcast.
__global__ __launch_bounds__(256) void k_gemm2(
    const float* __restrict__ W2, const float* __restrict__ as2,
    const float* __restrict__ ad2, int n)
{
    __shared__ float4 Ws[64 * 32];
    __shared__ float atts[128], attd[128];
    int t = threadIdx.x, w = t >> 5, l = t & 31;
    const float4* Wv = (const float4*)W2;
    for (int i = t; i < 2048; i += 256) Ws[i] = Wv[i];
    if (t < 128) { atts[t] = as2[t]; attd[t] = ad2[t]; }
    __syncthreads();
    int ntiles = (n + 3) >> 2;
    for (int tile = blockIdx.x * 8 + w; tile < ntiles; tile += gridDim.x * 8) {
        int row0 = tile * 4;
        float xr[4][2];
#pragma unroll
        for (int r = 0; r < 4; r++) {
            const float* xp = d_x1 + (size_t)min(row0 + r, n - 1) * 64;
#pragma unroll
            for (int c = 0; c < 2; c++) xr[r][c] = xp[l + 32 * c];
        }
        float4 acc[4] = {{0,0,0,0},{0,0,0,0},{0,0,0,0},{0,0,0,0}};
#pragma unroll
        for (int c = 0; c < 2; c++) {
#pragma unroll 8
            for (int kk = 0; kk < 32; kk++) {
                float4 wv = Ws[(c * 32 + kk) * 32 + l];
#pragma unroll
                for (int r = 0; r < 4; r++) {
                    float xv = __shfl_sync(0xffffffffu, xr[r][c], kk);
                    acc[r].x += xv * wv.x; acc[r].y += xv * wv.y;
                    acc[r].z += xv * wv.z; acc[r].w += xv * wv.w;
                }
            }
        }
#pragma unroll
        for (int r = 0; r < 4; r++) {
            int row = row0 + r;
            if (row >= n) break;
            ((float4*)(d_h2 + (size_t)row * 128))[l] = acc[r];
            float ps = acc[r].x * atts[4 * l]     + acc[r].y * atts[4 * l + 1]
                     + acc[r].z * atts[4 * l + 2] + acc[r].w * atts[4 * l + 3];
            float pd = acc[r].x * attd[4 * l]     + acc[r].y * attd[4 * l + 1]
                     + acc[r].z * attd[4 * l + 2] + acc[r].w * attd[4 * l + 3];
#pragma unroll
            for (int o = 16; o; o >>= 1) {
                ps += __shfl_xor_sync(0xffffffffu, ps, o);
                pd += __shfl_xor_sync(0xffffffffu, pd, o);
            }
            if (l == 0) { d_as2[row] = ps; d_ad2[row] = pd; }
        }
    }
}

// --------------------------- Layer 2 aggregate ---------------------------
// warp per dst node; lane l owns channels 4l..4l+3; H=1 -> scalar alpha
__global__ __launch_bounds__(256) void k_agg2(
    const float* __restrict__ bias2, float* __restrict__ out, int n)
{
    int t = threadIdx.x, w = t >> 5, l = t & 31;
    int node = blockIdx.x * 8 + w;
    if (node >= n) return;
    float adv = d_ad2[node];
    int beg = d_off[node], end = d_off[node + 1];
    float c0 = 0.f, c1 = 0.f, c2 = 0.f, c3 = 0.f;
    float dpart = 0.f;
    for (int ch = beg; ch < end; ch += 32) {
        int gi = ch + l;
        int idx = -1;
        float e = 0.f;
        if (gi < end) {
            idx = d_ssrc[gi];
            float al = d_as2[idx] + adv;
            al = (al >= 0.f) ? al : 0.2f * al;
            e = __expf(al);
            dpart += e;
        }
        int cnt = min(32, end - ch);
        for (int j = 0; j < cnt; j++) {
            int s = __shfl_sync(0xffffffffu, idx, j);
            float ev = __shfl_sync(0xffffffffu, e, j);
            float4 hv = ((const float4*)(d_h2 + (size_t)s * 128))[l];
            c0 += ev * hv.x; c1 += ev * hv.y;
            c2 += ev * hv.z; c3 += ev * hv.w;
        }
    }
#pragma unroll
    for (int o = 16; o; o >>= 1) dpart += __shfl_xor_sync(0xffffffffu, dpart, o);
    float inv = 1.f / (dpart + 1e-16f);
    float4 b = ((const float4*)bias2)[l];
    float4 o4 = make_float4(c0 * inv + b.x, c1 * inv + b.y,
                            c2 * inv + b.z, c3 * inv + b.w);
    ((float4*)(out + (size_t)node * 128))[l] = o4;
}

// ------------------------------- launch ----------------------------------
extern "C" void kernel_launch(void* const* d_in, const int* in_sizes, int n_in,
                              void* d_out, int out_size)
{
    const float* x    = (const float*)d_in[0];
    const int*   ei   = (const int*)d_in[1];     // JAX default: int64 request -> int32
    const float* W1   = (const float*)d_in[2];
    const float* asr1 = (const float*)d_in[3];
    const float* ads1 = (const float*)d_in[4];
    const float* b1   = (const float*)d_in[5];
    const float* W2   = (const float*)d_in[6];
    const float* asr2 = (const float*)d_in[7];
    const float* ads2 = (const float*)d_in[8];
    const float* b2   = (const float*)d_in[9];
    float* out = (float*)d_out;

    int N  = in_sizes[0] / 128;
    int E  = in_sizes[1] / 2;
    int vec = ((E & 3) == 0) ? 1 : 0;
    int e4 = (E + 3) / 4;

    // CSR by destination (self loops placed as slot 0 of each segment by k_scan)
    k_zero_deg<<<(N + 255) / 256, 256>>>(N);
    k_hist<<<(e4 + 255) / 256, 256>>>(ei, E, vec);
    k_scan<<<1, 1024>>>(N);
    k_scatter<<<(e4 + 255) / 256, 256>>>(ei, E, vec);

    // Layer 1
    int ntb = ((N + 3) / 4 + 7) / 8;
    k_gemm1<<<ntb, 256>>>(x, W1, asr1, ads1, N);
    k_agg1<<<(N + 7) / 8, 256>>>(b1, N);

    // Layer 2
    k_gemm2<<<ntb, 256>>>(W2, asr2, ads2, N);
    k_agg2<<<(N + 7) / 8, 256>>>(b2, out, N);
}

// round 4
// speedup vs baseline: 1.0678x; 1.0259x over previous
#include <cuda_runtime.h>
#include <math.h>

// Problem-fixed maxima (setup_inputs: N=50000, E=1600000, +N self loops)
#define MAXN 50048
#define MAXE 1650048

// ------------ static device scratch (no allocations allowed) -------------
__device__ float d_h1[MAXN * 64];    // layer1 projected features [N,64]
__device__ float d_as1[MAXN * 8];    // layer1 a_src  [N,8]
__device__ float d_ad1[MAXN * 8];    // layer1 a_dst  [N,8]
__device__ float d_x1[MAXN * 64];    // layer1 output after bias+ELU [N,64]
__device__ float d_h2[MAXN * 128];   // layer2 projected features [N,128]
__device__ float d_as2[MAXN];        // layer2 a_src [N]
__device__ float d_ad2[MAXN];        // layer2 a_dst [N]
__device__ int   d_deg[MAXN];
__device__ int   d_off[MAXN + 1];
__device__ int   d_cur[MAXN];
__device__ int   d_ssrc[MAXE];       // src node ids grouped by dst (CSR)

// ---------------------------- CSR build ----------------------------------
__global__ void k_zero_deg(int n) {
    int i = blockIdx.x * blockDim.x + threadIdx.x;
    if (i < n) d_deg[i] = 0;
}

// histogram of real edges only (self loops handled in scan)
__global__ void k_hist(const int* __restrict__ ei, int E, int vec) {
    int i = blockIdx.x * blockDim.x + threadIdx.x;
    int e = i * 4;
    if (e >= E) return;
    if (vec && e + 3 < E) {
        int4 d = *(const int4*)(ei + E + e);
        atomicAdd(&d_deg[d.x], 1);
        atomicAdd(&d_deg[d.y], 1);
        atomicAdd(&d_deg[d.z], 1);
        atomicAdd(&d_deg[d.w], 1);
    } else {
        for (int j = e; j < E && j < e + 4; j++)
            atomicAdd(&d_deg[ei[E + j]], 1);
    }
}

// single-block 1024-thread warp-shuffle scan; also places self loop as slot 0
// of each segment and initializes cursors past it.
__global__ __launch_bounds__(1024) void k_scan(int n) {
    __shared__ int warpsum[32];
    int t = threadIdx.x, lane = t & 31, wid = t >> 5;
    int ipt = (n + 1023) >> 10;
    int start = t * ipt;
    int endi  = min(start + ipt, n);
    int s = 0;
    for (int i = start; i < endi; i++) s += d_deg[i] + 1;
    int incl = s;
#pragma unroll
    for (int o = 1; o < 32; o <<= 1) {
        int v = __shfl_up_sync(0xffffffffu, incl, o);
        if (lane >= o) incl += v;
    }
    if (lane == 31) warpsum[wid] = incl;
    __syncthreads();
    if (wid == 0) {
        int v = warpsum[lane];
        int wi = v;
#pragma unroll
        for (int o = 1; o < 32; o <<= 1) {
            int u = __shfl_up_sync(0xffffffffu, wi, o);
            if (lane >= o) wi += u;
        }
        warpsum[lane] = wi - v;  // exclusive
    }
    __syncthreads();
    int run = warpsum[wid] + (incl - s);
    for (int i = start; i < endi; i++) {
        int d = d_deg[i];
        d_off[i]  = run;
        d_ssrc[run] = i;       // self loop occupies slot 0 of the segment
        d_cur[i]  = run + 1;
        run += d + 1;
    }
    if (t == 1023) d_off[n] = run;
}

__global__ void k_scatter(const int* __restrict__ ei, int E, int vec) {
    int i = blockIdx.x * blockDim.x + threadIdx.x;
    int e = i * 4;
    if (e >= E) return;
    if (vec && e + 3 < E) {
        int4 s = *(const int4*)(ei + e);
        int4 d = *(const int4*)(ei + E + e);
        d_ssrc[atomicAdd(&d_cur[d.x], 1)] = s.x;
        d_ssrc[atomicAdd(&d_cur[d.y], 1)] = s.y;
        d_ssrc[atomicAdd(&d_cur[d.z], 1)] = s.z;
        d_ssrc[atomicAdd(&d_cur[d.w], 1)] = s.w;
    } else {
        for (int j = e; j < E && j < e + 4; j++)
            d_ssrc[atomicAdd(&d_cur[ei[E + j]], 1)] = ei[j];
    }
}

// ---------------------------- Layer 1 GEMM -------------------------------
__global__ __launch_bounds__(256) void k_gemm1(
    const float* __restrict__ x, const float* __restrict__ W1,
    const float* __restrict__ as, const float* __restrict__ ad, int n)
{
    __shared__ float2 Ws[128 * 32];
    __shared__ float atts[64], attd[64];
    int t = threadIdx.x, w = t >> 5, l = t & 31;
    const float2* Wv = (const float2*)W1;
    for (int i = t; i < 4096; i += 256) Ws[i] = Wv[i];
    if (t < 64) { atts[t] = as[t]; attd[t] = ad[t]; }
    __syncthreads();
    int ntiles = (n + 3) >> 2;
    for (int tile = blockIdx.x * 8 + w; tile < ntiles; tile += gridDim.x * 8) {
        int row0 = tile * 4;
        float xr[4][4];
#pragma unroll
        for (int r = 0; r < 4; r++) {
            const float* xp = x + (size_t)min(row0 + r, n - 1) * 128;
#pragma unroll
            for (int c = 0; c < 4; c++) xr[r][c] = xp[l + 32 * c];
        }
        float2 acc[4] = {{0,0},{0,0},{0,0},{0,0}};
#pragma unroll
        for (int c = 0; c < 4; c++) {
#pragma unroll 8
            for (int kk = 0; kk < 32; kk++) {
                float2 wv = Ws[(c * 32 + kk) * 32 + l];
#pragma unroll
                for (int r = 0; r < 4; r++) {
                    float xv = __shfl_sync(0xffffffffu, xr[r][c], kk);
                    acc[r].x += xv * wv.x;
                    acc[r].y += xv * wv.y;
                }
            }
        }
#pragma unroll
        for (int r = 0; r < 4; r++) {
            int row = row0 + r;
            if (row >= n) break;
            ((float2*)(d_h1 + (size_t)row * 64))[l] = acc[r];
            float ps = acc[r].x * atts[2 * l] + acc[r].y * atts[2 * l + 1];
            float pd = acc[r].x * attd[2 * l] + acc[r].y * attd[2 * l + 1];
            ps += __shfl_xor_sync(0xffffffffu, ps, 1);
            ps += __shfl_xor_sync(0xffffffffu, ps, 2);
            pd += __shfl_xor_sync(0xffffffffu, pd, 1);
            pd += __shfl_xor_sync(0xffffffffu, pd, 2);
            if ((l & 3) == 0) {
                d_as1[row * 8 + (l >> 2)] = ps;
                d_ad1[row * 8 + (l >> 2)] = pd;
            }
        }
    }
}

// --------------------------- Layer 1 aggregate ---------------------------
// warp per dst node; lane l owns channels 2l,2l+1 (head = l>>2).
// Fast path for full 32-edge chunks: batched exps + 4-way independent LDGs.
__global__ __launch_bounds__(256) void k_agg1(const float* __restrict__ bias1, int n) {
    int t = threadIdx.x, w = t >> 5, l = t & 31;
    int node = blockIdx.x * 8 + w;
    if (node >= n) return;
    int hl = l >> 2;
    float adv = d_ad1[node * 8 + (l & 7)];
    int beg = d_off[node], end = d_off[node + 1];
    float acc0 = 0.f, acc1 = 0.f, dsum = 0.f;
    int ch = beg;
    for (; ch + 32 <= end; ch += 32) {
        int idx = d_ssrc[ch + l];
        float ec[8];
#pragma unroll
        for (int g = 0; g < 8; g++) {
            int sA = __shfl_sync(0xffffffffu, idx, g * 4 + (l >> 3));
            float al = __ldg(&d_as1[sA * 8 + (l & 7)]) + adv;
            al = (al >= 0.f) ? al : 0.2f * al;
            ec[g] = __expf(al);
        }
#pragma unroll
        for (int g = 0; g < 8; g++) {
            int s0 = __shfl_sync(0xffffffffu, idx, g * 4 + 0);
            int s1 = __shfl_sync(0xffffffffu, idx, g * 4 + 1);
            int s2 = __shfl_sync(0xffffffffu, idx, g * 4 + 2);
            int s3 = __shfl_sync(0xffffffffu, idx, g * 4 + 3);
            float2 h0 = ((const float2*)(d_h1 + (size_t)s0 * 64))[l];
            float2 h1 = ((const float2*)(d_h1 + (size_t)s1 * 64))[l];
            float2 h2 = ((const float2*)(d_h1 + (size_t)s2 * 64))[l];
            float2 h3 = ((const float2*)(d_h1 + (size_t)s3 * 64))[l];
            float ev0 = __shfl_sync(0xffffffffu, ec[g], 0 * 8 + hl);
            float ev1 = __shfl_sync(0xffffffffu, ec[g], 1 * 8 + hl);
            float ev2 = __shfl_sync(0xffffffffu, ec[g], 2 * 8 + hl);
            float ev3 = __shfl_sync(0xffffffffu, ec[g], 3 * 8 + hl);
            acc0 += ev0 * h0.x; acc1 += ev0 * h0.y;
            acc0 += ev1 * h1.x; acc1 += ev1 * h1.y;
            acc0 += ev2 * h2.x; acc1 += ev2 * h2.y;
            acc0 += ev3 * h3.x; acc1 += ev3 * h3.y;
            dsum += (ev0 + ev1) + (ev2 + ev3);
        }
    }
    if (ch < end) {   // tail (<32 edges), serial
        int cnt = end - ch;
        int gi = ch + l;
        int idx = (gi < end) ? d_ssrc[gi] : 0;
        for (int j4 = 0; j4 < 8; j4++) {
            if (j4 * 4 >= cnt) break;
            int ka = j4 * 4 + (l >> 3);
            int sA = __shfl_sync(0xffffffffu, idx, j4 * 4 + (l >> 3));
            float e = 0.f;
            if (ka < cnt) {
                float al = d_as1[sA * 8 + (l & 7)] + adv;
                al = (al >= 0.f) ? al : 0.2f * al;
                e = __expf(al);
            }
#pragma unroll
            for (int j = 0; j < 4; j++) {
                if (j4 * 4 + j >= cnt) break;
                int s = __shfl_sync(0xffffffffu, idx, j4 * 4 + j);
                float ev = __shfl_sync(0xffffffffu, e, j * 8 + hl);
                float2 hv = ((const float2*)(d_h1 + (size_t)s * 64))[l];
                acc0 += ev * hv.x;
                acc1 += ev * hv.y;
                dsum += ev;
            }
        }
    }
    float inv = 1.f / (dsum + 1e-16f);
    float o0 = acc0 * inv + bias1[2 * l];
    float o1 = acc1 * inv + bias1[2 * l + 1];
    o0 = (o0 > 0.f) ? o0 : expm1f(o0);
    o1 = (o1 > 0.f) ? o1 : expm1f(o1);
    ((float2*)(d_x1 + (size_t)node * 64))[l] = make_float2(o0, o1);
}

// ---------------------------- Layer 2 GEMM -------------------------------
__global__ __launch_bounds__(256) void k_gemm2(
    const float* __restrict__ W2, const float* __restrict__ as2,
    const float* __restrict__ ad2, int n)
{
    __shared__ float4 Ws[64 * 32];
    __shared__ float atts[128], attd[128];
    int t = threadIdx.x, w = t >> 5, l = t & 31;
    const float4* Wv = (const float4*)W2;
    for (int i = t; i < 2048; i += 256) Ws[i] = Wv[i];
    if (t < 128) { atts[t] = as2[t]; attd[t] = ad2[t]; }
    __syncthreads();
    int ntiles = (n + 3) >> 2;
    for (int tile = blockIdx.x * 8 + w; tile < ntiles; tile += gridDim.x * 8) {
        int row0 = tile * 4;
        float xr[4][2];
#pragma unroll
        for (int r = 0; r < 4; r++) {
            const float* xp = d_x1 + (size_t)min(row0 + r, n - 1) * 64;
#pragma unroll
            for (int c = 0; c < 2; c++) xr[r][c] = xp[l + 32 * c];
        }
        float4 acc[4] = {{0,0,0,0},{0,0,0,0},{0,0,0,0},{0,0,0,0}};
#pragma unroll
        for (int c = 0; c < 2; c++) {
#pragma unroll 8
            for (int kk = 0; kk < 32; kk++) {
                float4 wv = Ws[(c * 32 + kk) * 32 + l];
#pragma unroll
                for (int r = 0; r < 4; r++) {
                    float xv = __shfl_sync(0xffffffffu, xr[r][c], kk);
                    acc[r].x += xv * wv.x; acc[r].y += xv * wv.y;
                    acc[r].z += xv * wv.z; acc[r].w += xv * wv.w;
                }
            }
        }
#pragma unroll
        for (int r = 0; r < 4; r++) {
            int row = row0 + r;
            if (row >= n) break;
            ((float4*)(d_h2 + (size_t)row * 128))[l] = acc[r];
            float ps = acc[r].x * atts[4 * l]     + acc[r].y * atts[4 * l + 1]
                     + acc[r].z * atts[4 * l + 2] + acc[r].w * atts[4 * l + 3];
            float pd = acc[r].x * attd[4 * l]     + acc[r].y * attd[4 * l + 1]
                     + acc[r].z * attd[4 * l + 2] + acc[r].w * attd[4 * l + 3];
#pragma unroll
            for (int o = 16; o; o >>= 1) {
                ps += __shfl_xor_sync(0xffffffffu, ps, o);
                pd += __shfl_xor_sync(0xffffffffu, pd, o);
            }
            if (l == 0) { d_as2[row] = ps; d_ad2[row] = pd; }
        }
    }
}

// --------------------------- Layer 2 aggregate ---------------------------
// warp per dst node; lane l owns channels 4l..4l+3; H=1 -> scalar alpha.
// Fast path for full 32-edge chunks with 4-way independent LDG.128s.
__global__ __launch_bounds__(256) void k_agg2(
    const float* __restrict__ bias2, float* __restrict__ out, int n)
{
    int t = threadIdx.x, w = t >> 5, l = t & 31;
    int node = blockIdx.x * 8 + w;
    if (node >= n) return;
    float adv = d_ad2[node];
    int beg = d_off[node], end = d_off[node + 1];
    float c0 = 0.f, c1 = 0.f, c2 = 0.f, c3 = 0.f;
    float dpart = 0.f;
    int ch = beg;
    for (; ch + 32 <= end; ch += 32) {
        int idx = d_ssrc[ch + l];
        float al = __ldg(&d_as2[idx]) + adv;
        al = (al >= 0.f) ? al : 0.2f * al;
        float e = __expf(al);
        dpart += e;
#pragma unroll
        for (int g = 0; g < 8; g++) {
            int s0 = __shfl_sync(0xffffffffu, idx, g * 4 + 0);
            int s1 = __shfl_sync(0xffffffffu, idx, g * 4 + 1);
            int s2 = __shfl_sync(0xffffffffu, idx, g * 4 + 2);
            int s3 = __shfl_sync(0xffffffffu, idx, g * 4 + 3);
            float ev0 = __shfl_sync(0xffffffffu, e, g * 4 + 0);
            float ev1 = __shfl_sync(0xffffffffu, e, g * 4 + 1);
            float ev2 = __shfl_sync(0xffffffffu, e, g * 4 + 2);
            float ev3 = __shfl_sync(0xffffffffu, e, g * 4 + 3);
            float4 h0 = ((const float4*)(d_h2 + (size_t)s0 * 128))[l];
            float4 h1 = ((const float4*)(d_h2 + (size_t)s1 * 128))[l];
            float4 h2 = ((const float4*)(d_h2 + (size_t)s2 * 128))[l];
            float4 h3 = ((const float4*)(d_h2 + (size_t)s3 * 128))[l];
            c0 += ev0 * h0.x; c1 += ev0 * h0.y; c2 += ev0 * h0.z; c3 += ev0 * h0.w;
            c0 += ev1 * h1.x; c1 += ev1 * h1.y; c2 += ev1 * h1.z; c3 += ev1 * h1.w;
            c0 += ev2 * h2.x; c1 += ev2 * h2.y; c2 += ev2 * h2.z; c3 += ev2 * h2.w;
            c0 += ev3 * h3.x; c1 += ev3 * h3.y; c2 += ev3 * h3.z; c3 += ev3 * h3.w;
        }
    }
    if (ch < end) {  // tail
        int gi = ch + l;
        int idx = -1;
        float e = 0.f;
        if (gi < end) {
            idx = d_ssrc[gi];
            float al = d_as2[idx] + adv;
            al = (al >= 0.f) ? al : 0.2f * al;
            e = __expf(al);
            dpart += e;
        }
        int cnt = end - ch;
        for (int j = 0; j < cnt; j++) {
            int s = __shfl_sync(0xffffffffu, idx, j);
            float ev = __shfl_sync(0xffffffffu, e, j);
            float4 hv = ((const float4*)(d_h2 + (size_t)s * 128))[l];
            c0 += ev * hv.x; c1 += ev * hv.y;
            c2 += ev * hv.z; c3 += ev * hv.w;
        }
    }
#pragma unroll
    for (int o = 16; o; o >>= 1) dpart += __shfl_xor_sync(0xffffffffu, dpart, o);
    float inv = 1.f / (dpart + 1e-16f);
    float4 b = ((const float4*)bias2)[l];
    float4 o4 = make_float4(c0 * inv + b.x, c1 * inv + b.y,
                            c2 * inv + b.z, c3 * inv + b.w);
    ((float4*)(out + (size_t)node * 128))[l] = o4;
}

// ------------------------------- launch ----------------------------------
extern "C" void kernel_launch(void* const* d_in, const int* in_sizes, int n_in,
                              void* d_out, int out_size)
{
    const float* x    = (const float*)d_in[0];
    const int*   ei   = (const int*)d_in[1];     // JAX default: int64 request -> int32
    const float* W1   = (const float*)d_in[2];
    const float* asr1 = (const float*)d_in[3];
    const float* ads1 = (const float*)d_in[4];
    const float* b1   = (const float*)d_in[5];
    const float* W2   = (const float*)d_in[6];
    const float* asr2 = (const float*)d_in[7];
    const float* ads2 = (const float*)d_in[8];
    const float* b2   = (const float*)d_in[9];
    float* out = (float*)d_out;

    int N  = in_sizes[0] / 128;
    int E  = in_sizes[1] / 2;
    int vec = ((E & 3) == 0) ? 1 : 0;
    int e4 = (E + 3) / 4;

    // CSR by destination (self loops placed as slot 0 of each segment by k_scan)
    k_zero_deg<<<(N + 255) / 256, 256>>>(N);
    k_hist<<<(e4 + 255) / 256, 256>>>(ei, E, vec);
    k_scan<<<1, 1024>>>(N);
    k_scatter<<<(e4 + 255) / 256, 256>>>(ei, E, vec);

    // Layer 1
    int ntb = ((N + 3) / 4 + 7) / 8;
    k_gemm1<<<ntb, 256>>>(x, W1, asr1, ads1, N);
    k_agg1<<<(N + 7) / 8, 256>>>(b1, N);

    // Layer 2
    k_gemm2<<<ntb, 256>>>(W2, asr2, ads2, N);
    k_agg2<<<(N + 7) / 8, 256>>>(b2, out, N);
}

// round 5
// speedup vs baseline: 1.1005x; 1.0307x over previous
#include <cuda_runtime.h>
#include <math.h>

// Problem-fixed maxima (setup_inputs: N=50000, E=1600000, +N self loops)
#define MAXN 50048
#define MAXE 1650080

// ------------ static device scratch (no allocations allowed) -------------
__device__ float d_h1[MAXN * 64];
__device__ float d_as1[MAXN * 8];
__device__ float d_ad1[MAXN * 8];
__device__ float d_x1[MAXN * 64];
__device__ float d_h2[MAXN * 128];
__device__ float d_as2[MAXN];
__device__ float d_ad2[MAXN];
__device__ int   d_deg[MAXN];
__device__ int   d_off[MAXN + 1];
__device__ int   d_cur[MAXN];
__device__ int   d_ssrc[MAXE];

// ---------------------------- CSR build ----------------------------------
__global__ void k_zero_deg(int n) {
    int i = blockIdx.x * blockDim.x + threadIdx.x;
    if (i < n) d_deg[i] = 0;
}

// histogram of real edges only (self loops handled in scan); 8 edges/thread
__global__ void k_hist(const int* __restrict__ ei, int E, int vec) {
    int i = blockIdx.x * blockDim.x + threadIdx.x;
    int e = i * 8;
    if (e >= E) return;
    if (vec && e + 7 < E) {
        int4 d0 = *(const int4*)(ei + E + e);
        int4 d1 = *(const int4*)(ei + E + e + 4);
        atomicAdd(&d_deg[d0.x], 1); atomicAdd(&d_deg[d0.y], 1);
        atomicAdd(&d_deg[d0.z], 1); atomicAdd(&d_deg[d0.w], 1);
        atomicAdd(&d_deg[d1.x], 1); atomicAdd(&d_deg[d1.y], 1);
        atomicAdd(&d_deg[d1.z], 1); atomicAdd(&d_deg[d1.w], 1);
    } else {
        for (int j = e; j < E && j < e + 8; j++)
            atomicAdd(&d_deg[ei[E + j]], 1);
    }
}

// single-block 1024-thread warp-shuffle scan; places self loop at slot 0
__global__ __launch_bounds__(1024) void k_scan(int n) {
    __shared__ int warpsum[32];
    int t = threadIdx.x, lane = t & 31, wid = t >> 5;
    int ipt = (n + 1023) >> 10;
    int start = t * ipt;
    int endi  = min(start + ipt, n);
    int s = 0;
    for (int i = start; i < endi; i++) s += d_deg[i] + 1;
    int incl = s;
#pragma unroll
    for (int o = 1; o < 32; o <<= 1) {
        int v = __shfl_up_sync(0xffffffffu, incl, o);
        if (lane >= o) incl += v;
    }
    if (lane == 31) warpsum[wid] = incl;
    __syncthreads();
    if (wid == 0) {
        int v = warpsum[lane];
        int wi = v;
#pragma unroll
        for (int o = 1; o < 32; o <<= 1) {
            int u = __shfl_up_sync(0xffffffffu, wi, o);
            if (lane >= o) wi += u;
        }
        warpsum[lane] = wi - v;
    }
    __syncthreads();
    int run = warpsum[wid] + (incl - s);
    for (int i = start; i < endi; i++) {
        int d = d_deg[i];
        d_off[i]  = run;
        d_ssrc[run] = i;
        d_cur[i]  = run + 1;
        run += d + 1;
    }
    if (t == 1023) d_off[n] = run;
}

__global__ void k_scatter(const int* __restrict__ ei, int E, int vec) {
    int i = blockIdx.x * blockDim.x + threadIdx.x;
    int e = i * 8;
    if (e >= E) return;
    if (vec && e + 7 < E) {
        int4 s0 = *(const int4*)(ei + e);
        int4 s1 = *(const int4*)(ei + e + 4);
        int4 d0 = *(const int4*)(ei + E + e);
        int4 d1 = *(const int4*)(ei + E + e + 4);
        int p0 = atomicAdd(&d_cur[d0.x], 1);
        int p1 = atomicAdd(&d_cur[d0.y], 1);
        int p2 = atomicAdd(&d_cur[d0.z], 1);
        int p3 = atomicAdd(&d_cur[d0.w], 1);
        int p4 = atomicAdd(&d_cur[d1.x], 1);
        int p5 = atomicAdd(&d_cur[d1.y], 1);
        int p6 = atomicAdd(&d_cur[d1.z], 1);
        int p7 = atomicAdd(&d_cur[d1.w], 1);
        d_ssrc[p0] = s0.x; d_ssrc[p1] = s0.y; d_ssrc[p2] = s0.z; d_ssrc[p3] = s0.w;
        d_ssrc[p4] = s1.x; d_ssrc[p5] = s1.y; d_ssrc[p6] = s1.z; d_ssrc[p7] = s1.w;
    } else {
        for (int j = e; j < E && j < e + 8; j++)
            d_ssrc[atomicAdd(&d_cur[ei[E + j]], 1)] = ei[j];
    }
}

// ---------------------------- Layer 1 GEMM -------------------------------
__global__ __launch_bounds__(256) void k_gemm1(
    const float* __restrict__ x, const float* __restrict__ W1,
    const float* __restrict__ as, const float* __restrict__ ad, int n)
{
    __shared__ float2 Ws[128 * 32];
    __shared__ float atts[64], attd[64];
    int t = threadIdx.x, w = t >> 5, l = t & 31;
    const float2* Wv = (const float2*)W1;
    for (int i = t; i < 4096; i += 256) Ws[i] = Wv[i];
    if (t < 64) { atts[t] = as[t]; attd[t] = ad[t]; }
    __syncthreads();
    int ntiles = (n + 3) >> 2;
    for (int tile = blockIdx.x * 8 + w; tile < ntiles; tile += gridDim.x * 8) {
        int row0 = tile * 4;
        float xr[4][4];
#pragma unroll
        for (int r = 0; r < 4; r++) {
            const float* xp = x + (size_t)min(row0 + r, n - 1) * 128;
#pragma unroll
            for (int c = 0; c < 4; c++) xr[r][c] = xp[l + 32 * c];
        }
        float2 acc[4] = {{0,0},{0,0},{0,0},{0,0}};
#pragma unroll
        for (int c = 0; c < 4; c++) {
#pragma unroll 8
            for (int kk = 0; kk < 32; kk++) {
                float2 wv = Ws[(c * 32 + kk) * 32 + l];
#pragma unroll
                for (int r = 0; r < 4; r++) {
                    float xv = __shfl_sync(0xffffffffu, xr[r][c], kk);
                    acc[r].x += xv * wv.x;
                    acc[r].y += xv * wv.y;
                }
            }
        }
#pragma unroll
        for (int r = 0; r < 4; r++) {
            int row = row0 + r;
            if (row >= n) break;
            ((float2*)(d_h1 + (size_t)row * 64))[l] = acc[r];
            float ps = acc[r].x * atts[2 * l] + acc[r].y * atts[2 * l + 1];
            float pd = acc[r].x * attd[2 * l] + acc[r].y * attd[2 * l + 1];
            ps += __shfl_xor_sync(0xffffffffu, ps, 1);
            ps += __shfl_xor_sync(0xffffffffu, ps, 2);
            pd += __shfl_xor_sync(0xffffffffu, pd, 1);
            pd += __shfl_xor_sync(0xffffffffu, pd, 2);
            if ((l & 3) == 0) {
                d_as1[row * 8 + (l >> 2)] = ps;
                d_ad1[row * 8 + (l >> 2)] = pd;
            }
        }
    }
}

// --------------------------- Layer 1 aggregate ---------------------------
// warp per dst node; lane l owns channels 2l,2l+1 (head = l>>2).
// Single unified loop: predicated exps, 4-wide independent gathers, no tail.
__global__ __launch_bounds__(256) void k_agg1(const float* __restrict__ bias1, int n) {
    int t = threadIdx.x, w = t >> 5, l = t & 31;
    int node = blockIdx.x * 8 + w;
    if (node >= n) return;
    int hl = l >> 2;
    float adv = d_ad1[node * 8 + (l & 7)];
    int beg = d_off[node], end = d_off[node + 1];
    float acc0 = 0.f, acc1 = 0.f, dsum = 0.f;
    for (int ch = beg; ch < end; ch += 32) {
        int cnt = end - ch;                       // >=1; may exceed 32
        int idx = d_ssrc[min(ch + l, end - 1)];   // always valid
        float ec[8];
#pragma unroll
        for (int g = 0; g < 8; g++) {
            int ka = g * 4 + (l >> 3);
            int sA = __shfl_sync(0xffffffffu, idx, g * 4 + (l >> 3));
            float e = 0.f;
            if (ka < cnt) {
                float al = __ldg(&d_as1[sA * 8 + (l & 7)]) + adv;
                al = (al >= 0.f) ? al : 0.2f * al;
                e = __expf(al);
            }
            ec[g] = e;
        }
#pragma unroll
        for (int g = 0; g < 8; g++) {
            if (g * 4 >= cnt) break;
            int s0 = __shfl_sync(0xffffffffu, idx, g * 4 + 0);
            int s1 = __shfl_sync(0xffffffffu, idx, g * 4 + 1);
            int s2 = __shfl_sync(0xffffffffu, idx, g * 4 + 2);
            int s3 = __shfl_sync(0xffffffffu, idx, g * 4 + 3);
            float2 h0 = ((const float2*)(d_h1 + (size_t)s0 * 64))[l];
            float2 h1 = ((const float2*)(d_h1 + (size_t)s1 * 64))[l];
            float2 h2 = ((const float2*)(d_h1 + (size_t)s2 * 64))[l];
            float2 h3 = ((const float2*)(d_h1 + (size_t)s3 * 64))[l];
            float ev0 = __shfl_sync(0xffffffffu, ec[g], 0 * 8 + hl);
            float ev1 = __shfl_sync(0xffffffffu, ec[g], 1 * 8 + hl);
            float ev2 = __shfl_sync(0xffffffffu, ec[g], 2 * 8 + hl);
            float ev3 = __shfl_sync(0xffffffffu, ec[g], 3 * 8 + hl);
            acc0 += ev0 * h0.x; acc1 += ev0 * h0.y;
            acc0 += ev1 * h1.x; acc1 += ev1 * h1.y;
            acc0 += ev2 * h2.x; acc1 += ev2 * h2.y;
            acc0 += ev3 * h3.x; acc1 += ev3 * h3.y;
            dsum += (ev0 + ev1) + (ev2 + ev3);
        }
    }
    float inv = 1.f / (dsum + 1e-16f);
    float o0 = acc0 * inv + bias1[2 * l];
    float o1 = acc1 * inv + bias1[2 * l + 1];
    o0 = (o0 > 0.f) ? o0 : expm1f(o0);
    o1 = (o1 > 0.f) ? o1 : expm1f(o1);
    ((float2*)(d_x1 + (size_t)node * 64))[l] = make_float2(o0, o1);
}

// ---------------------------- Layer 2 GEMM -------------------------------
__global__ __launch_bounds__(256) void k_gemm2(
    const float* __restrict__ W2, const float* __restrict__ as2,
    const float* __restrict__ ad2, int n)
{
    __shared__ float4 Ws[64 * 32];
    __shared__ float atts[128], attd[128];
    int t = threadIdx.x, w = t >> 5, l = t & 31;
    const float4* Wv = (const float4*)W2;
    for (int i = t; i < 2048; i += 256) Ws[i] = Wv[i];
    if (t < 128) { atts[t] = as2[t]; attd[t] = ad2[t]; }
    __syncthreads();
    int ntiles = (n + 3) >> 2;
    for (int tile = blockIdx.x * 8 + w; tile < ntiles; tile += gridDim.x * 8) {
        int row0 = tile * 4;
        float xr[4][2];
#pragma unroll
        for (int r = 0; r < 4; r++) {
            const float* xp = d_x1 + (size_t)min(row0 + r, n - 1) * 64;
#pragma unroll
            for (int c = 0; c < 2; c++) xr[r][c] = xp[l + 32 * c];
        }
        float4 acc[4] = {{0,0,0,0},{0,0,0,0},{0,0,0,0},{0,0,0,0}};
#pragma unroll
        for (int c = 0; c < 2; c++) {
#pragma unroll 8
            for (int kk = 0; kk < 32; kk++) {
                float4 wv = Ws[(c * 32 + kk) * 32 + l];
#pragma unroll
                for (int r = 0; r < 4; r++) {
                    float xv = __shfl_sync(0xffffffffu, xr[r][c], kk);
                    acc[r].x += xv * wv.x; acc[r].y += xv * wv.y;
                    acc[r].z += xv * wv.z; acc[r].w += xv * wv.w;
                }
            }
        }
#pragma unroll
        for (int r = 0; r < 4; r++) {
            int row = row0 + r;
            if (row >= n) break;
            ((float4*)(d_h2 + (size_t)row * 128))[l] = acc[r];
            float ps = acc[r].x * atts[4 * l]     + acc[r].y * atts[4 * l + 1]
                     + acc[r].z * atts[4 * l + 2] + acc[r].w * atts[4 * l + 3];
            float pd = acc[r].x * attd[4 * l]     + acc[r].y * attd[4 * l + 1]
                     + acc[r].z * attd[4 * l + 2] + acc[r].w * attd[4 * l + 3];
#pragma unroll
            for (int o = 16; o; o >>= 1) {
                ps += __shfl_xor_sync(0xffffffffu, ps, o);
                pd += __shfl_xor_sync(0xffffffffu, pd, o);
            }
            if (l == 0) { d_as2[row] = ps; d_ad2[row] = pd; }
        }
    }
}

// --------------------------- Layer 2 aggregate ---------------------------
// warp per dst node; lane l owns channels 4l..4l+3; unified predicated loop.
__global__ __launch_bounds__(256) void k_agg2(
    const float* __restrict__ bias2, float* __restrict__ out, int n)
{
    int t = threadIdx.x, w = t >> 5, l = t & 31;
    int node = blockIdx.x * 8 + w;
    if (node >= n) return;
    float adv = d_ad2[node];
    int beg = d_off[node], end = d_off[node + 1];
    float c0 = 0.f, c1 = 0.f, c2 = 0.f, c3 = 0.f;
    float dpart = 0.f;
    for (int ch = beg; ch < end; ch += 32) {
        int cnt = end - ch;
        int idx = d_ssrc[min(ch + l, end - 1)];
        float e = 0.f;
        if (l < cnt) {
            float al = __ldg(&d_as2[idx]) + adv;
            al = (al >= 0.f) ? al : 0.2f * al;
            e = __expf(al);
            dpart += e;
        }
#pragma unroll
        for (int g = 0; g < 8; g++) {
            if (g * 4 >= cnt) break;
            int s0 = __shfl_sync(0xffffffffu, idx, g * 4 + 0);
            int s1 = __shfl_sync(0xffffffffu, idx, g * 4 + 1);
            int s2 = __shfl_sync(0xffffffffu, idx, g * 4 + 2);
            int s3 = __shfl_sync(0xffffffffu, idx, g * 4 + 3);
            float ev0 = __shfl_sync(0xffffffffu, e, g * 4 + 0);
            float ev1 = __shfl_sync(0xffffffffu, e, g * 4 + 1);
            float ev2 = __shfl_sync(0xffffffffu, e, g * 4 + 2);
            float ev3 = __shfl_sync(0xffffffffu, e, g * 4 + 3);
            float4 h0 = ((const float4*)(d_h2 + (size_t)s0 * 128))[l];
            float4 h1 = ((const float4*)(d_h2 + (size_t)s1 * 128))[l];
            float4 h2 = ((const float4*)(d_h2 + (size_t)s2 * 128))[l];
            float4 h3 = ((const float4*)(d_h2 + (size_t)s3 * 128))[l];
            c0 += ev0 * h0.x; c1 += ev0 * h0.y; c2 += ev0 * h0.z; c3 += ev0 * h0.w;
            c0 += ev1 * h1.x; c1 += ev1 * h1.y; c2 += ev1 * h1.z; c3 += ev1 * h1.w;
            c0 += ev2 * h2.x; c1 += ev2 * h2.y; c2 += ev2 * h2.z; c3 += ev2 * h2.w;
            c0 += ev3 * h3.x; c1 += ev3 * h3.y; c2 += ev3 * h3.z; c3 += ev3 * h3.w;
        }
    }
#pragma unroll
    for (int o = 16; o; o >>= 1) dpart += __shfl_xor_sync(0xffffffffu, dpart, o);
    float inv = 1.f / (dpart + 1e-16f);
    float4 b = ((const float4*)bias2)[l];
    float4 o4 = make_float4(c0 * inv + b.x, c1 * inv + b.y,
                            c2 * inv + b.z, c3 * inv + b.w);
    ((float4*)(out + (size_t)node * 128))[l] = o4;
}

// ------------------------------- launch ----------------------------------
extern "C" void kernel_launch(void* const* d_in, const int* in_sizes, int n_in,
                              void* d_out, int out_size)
{
    const float* x    = (const float*)d_in[0];
    const int*   ei   = (const int*)d_in[1];
    const float* W1   = (const float*)d_in[2];
    const float* asr1 = (const float*)d_in[3];
    const float* ads1 = (const float*)d_in[4];
    const float* b1   = (const float*)d_in[5];
    const float* W2   = (const float*)d_in[6];
    const float* asr2 = (const float*)d_in[7];
    const float* ads2 = (const float*)d_in[8];
    const float* b2   = (const float*)d_in[9];
    float* out = (float*)d_out;

    int N  = in_sizes[0] / 128;
    int E  = in_sizes[1] / 2;
    int vec = ((E & 7) == 0) ? 1 : 0;
    int e8 = (E + 7) / 8;

    k_zero_deg<<<(N + 255) / 256, 256>>>(N);
    k_hist<<<(e8 + 255) / 256, 256>>>(ei, E, vec);
    k_scan<<<1, 1024>>>(N);
    k_scatter<<<(e8 + 255) / 256, 256>>>(ei, E, vec);

    int ntb = ((N + 3) / 4 + 7) / 8;
    k_gemm1<<<ntb, 256>>>(x, W1, asr1, ads1, N);
    k_agg1<<<(N + 7) / 8, 256>>>(b1, N);

    k_gemm2<<<ntb, 256>>>(W2, asr2, ads2, N);
    k_agg2<<<(N + 7) / 8, 256>>>(b2, out, N);
}

// round 6
// speedup vs baseline: 1.1483x; 1.0434x over previous
#include <cuda_runtime.h>
#include <math.h>

// Problem-fixed maxima (setup_inputs: N=50000, E=1600000, +N self loops)
#define MAXN 50048
#define MAXE 1650080

// ------------ static device scratch (no allocations allowed) -------------
__device__ float d_h1[MAXN * 64];
__device__ float d_as1[MAXN * 8];
__device__ float d_ad1[MAXN * 8];
__device__ float d_x1[MAXN * 64];
__device__ float d_h2[MAXN * 128];
__device__ float d_as2[MAXN];
__device__ float d_ad2[MAXN];
__device__ int   d_deg[MAXN];
__device__ int   d_off[MAXN + 1];
__device__ int   d_cur[MAXN];
__device__ int   d_ssrc[MAXE];

// ---------------------------- CSR build ----------------------------------
__global__ void k_zero_deg(int n) {
    int i = blockIdx.x * blockDim.x + threadIdx.x;
    if (i < n) d_deg[i] = 0;
}

// histogram of real edges only (self loops handled in scan); 4 edges/thread
__global__ void k_hist(const int* __restrict__ ei, int E, int vec) {
    int i = blockIdx.x * blockDim.x + threadIdx.x;
    int e = i * 4;
    if (e >= E) return;
    if (vec && e + 3 < E) {
        int4 d = *(const int4*)(ei + E + e);
        atomicAdd(&d_deg[d.x], 1);
        atomicAdd(&d_deg[d.y], 1);
        atomicAdd(&d_deg[d.z], 1);
        atomicAdd(&d_deg[d.w], 1);
    } else {
        for (int j = e; j < E && j < e + 4; j++)
            atomicAdd(&d_deg[ei[E + j]], 1);
    }
}

// single-block 1024-thread warp-shuffle scan; places self loop at slot 0
__global__ __launch_bounds__(1024) void k_scan(int n) {
    __shared__ int warpsum[32];
    int t = threadIdx.x, lane = t & 31, wid = t >> 5;
    int ipt = (n + 1023) >> 10;
    int start = t * ipt;
    int endi  = min(start + ipt, n);
    int s = 0;
    for (int i = start; i < endi; i++) s += d_deg[i] + 1;
    int incl = s;
#pragma unroll
    for (int o = 1; o < 32; o <<= 1) {
        int v = __shfl_up_sync(0xffffffffu, incl, o);
        if (lane >= o) incl += v;
    }
    if (lane == 31) warpsum[wid] = incl;
    __syncthreads();
    if (wid == 0) {
        int v = warpsum[lane];
        int wi = v;
#pragma unroll
        for (int o = 1; o < 32; o <<= 1) {
            int u = __shfl_up_sync(0xffffffffu, wi, o);
            if (lane >= o) wi += u;
        }
        warpsum[lane] = wi - v;
    }
    __syncthreads();
    int run = warpsum[wid] + (incl - s);
    for (int i = start; i < endi; i++) {
        int d = d_deg[i];
        d_off[i]  = run;
        d_ssrc[run] = i;
        d_cur[i]  = run + 1;
        run += d + 1;
    }
    if (t == 1023) d_off[n] = run;
}

// ------------------- Fused Layer-1 GEMM + edge scatter --------------------
// blocks [0, ntb): h1 = x @ W1 (+ attention logits)
// blocks [ntb, ntb+sb): CSR scatter (independent work, different bottleneck)
__global__ __launch_bounds__(256) void k_gemm1_scatter(
    const float* __restrict__ x, const float* __restrict__ W1,
    const float* __restrict__ as, const float* __restrict__ ad, int n,
    const int* __restrict__ ei, int E, int vec, int ntb)
{
    __shared__ float2 Ws[128 * 32];
    __shared__ float atts[64], attd[64];
    int t = threadIdx.x;

    if (blockIdx.x >= ntb) {
        // ---- scatter part ----
        int i = (blockIdx.x - ntb) * blockDim.x + t;
        int e = i * 4;
        if (e >= E) return;
        if (vec && e + 3 < E) {
            int4 s = *(const int4*)(ei + e);
            int4 d = *(const int4*)(ei + E + e);
            d_ssrc[atomicAdd(&d_cur[d.x], 1)] = s.x;
            d_ssrc[atomicAdd(&d_cur[d.y], 1)] = s.y;
            d_ssrc[atomicAdd(&d_cur[d.z], 1)] = s.z;
            d_ssrc[atomicAdd(&d_cur[d.w], 1)] = s.w;
        } else {
            for (int j = e; j < E && j < e + 4; j++)
                d_ssrc[atomicAdd(&d_cur[ei[E + j]], 1)] = ei[j];
        }
        return;
    }

    // ---- gemm part ----
    int w = t >> 5, l = t & 31;
    const float2* Wv = (const float2*)W1;
    for (int i = t; i < 4096; i += 256) Ws[i] = Wv[i];
    if (t < 64) { atts[t] = as[t]; attd[t] = ad[t]; }
    __syncthreads();
    int ntiles = (n + 3) >> 2;
    for (int tile = blockIdx.x * 8 + w; tile < ntiles; tile += ntb * 8) {
        int row0 = tile * 4;
        float xr[4][4];
#pragma unroll
        for (int r = 0; r < 4; r++) {
            const float* xp = x + (size_t)min(row0 + r, n - 1) * 128;
#pragma unroll
            for (int c = 0; c < 4; c++) xr[r][c] = xp[l + 32 * c];
        }
        float2 acc[4] = {{0,0},{0,0},{0,0},{0,0}};
#pragma unroll
        for (int c = 0; c < 4; c++) {
#pragma unroll 8
            for (int kk = 0; kk < 32; kk++) {
                float2 wv = Ws[(c * 32 + kk) * 32 + l];
#pragma unroll
                for (int r = 0; r < 4; r++) {
                    float xv = __shfl_sync(0xffffffffu, xr[r][c], kk);
                    acc[r].x += xv * wv.x;
                    acc[r].y += xv * wv.y;
                }
            }
        }
#pragma unroll
        for (int r = 0; r < 4; r++) {
            int row = row0 + r;
            if (row >= n) break;
            ((float2*)(d_h1 + (size_t)row * 64))[l] = acc[r];
            float ps = acc[r].x * atts[2 * l] + acc[r].y * atts[2 * l + 1];
            float pd = acc[r].x * attd[2 * l] + acc[r].y * attd[2 * l + 1];
            ps += __shfl_xor_sync(0xffffffffu, ps, 1);
            ps += __shfl_xor_sync(0xffffffffu, ps, 2);
            pd += __shfl_xor_sync(0xffffffffu, pd, 1);
            pd += __shfl_xor_sync(0xffffffffu, pd, 2);
            if ((l & 3) == 0) {
                d_as1[row * 8 + (l >> 2)] = ps;
                d_ad1[row * 8 + (l >> 2)] = pd;
            }
        }
    }
}

// --------------------------- Layer 1 aggregate ---------------------------
// warp per dst node; lane l owns channels 2l,2l+1 (head = l>>2).
__global__ __launch_bounds__(256) void k_agg1(const float* __restrict__ bias1, int n) {
    int t = threadIdx.x, w = t >> 5, l = t & 31;
    int node = blockIdx.x * 8 + w;
    if (node >= n) return;
    int hl = l >> 2;
    float adv = d_ad1[node * 8 + (l & 7)];
    int beg = d_off[node], end = d_off[node + 1];
    float acc0 = 0.f, acc1 = 0.f, dsum = 0.f;
    for (int ch = beg; ch < end; ch += 32) {
        int cnt = end - ch;
        int idx = d_ssrc[min(ch + l, end - 1)];
        float ec[8];
#pragma unroll
        for (int g = 0; g < 8; g++) {
            int ka = g * 4 + (l >> 3);
            int sA = __shfl_sync(0xffffffffu, idx, g * 4 + (l >> 3));
            float e = 0.f;
            if (ka < cnt) {
                float al = __ldg(&d_as1[sA * 8 + (l & 7)]) + adv;
                al = (al >= 0.f) ? al : 0.2f * al;
                e = __expf(al);
            }
            ec[g] = e;
        }
#pragma unroll
        for (int g = 0; g < 8; g++) {
            if (g * 4 >= cnt) break;
            int s0 = __shfl_sync(0xffffffffu, idx, g * 4 + 0);
            int s1 = __shfl_sync(0xffffffffu, idx, g * 4 + 1);
            int s2 = __shfl_sync(0xffffffffu, idx, g * 4 + 2);
            int s3 = __shfl_sync(0xffffffffu, idx, g * 4 + 3);
            float2 h0 = ((const float2*)(d_h1 + (size_t)s0 * 64))[l];
            float2 h1 = ((const float2*)(d_h1 + (size_t)s1 * 64))[l];
            float2 h2 = ((const float2*)(d_h1 + (size_t)s2 * 64))[l];
            float2 h3 = ((const float2*)(d_h1 + (size_t)s3 * 64))[l];
            float ev0 = __shfl_sync(0xffffffffu, ec[g], 0 * 8 + hl);
            float ev1 = __shfl_sync(0xffffffffu, ec[g], 1 * 8 + hl);
            float ev2 = __shfl_sync(0xffffffffu, ec[g], 2 * 8 + hl);
            float ev3 = __shfl_sync(0xffffffffu, ec[g], 3 * 8 + hl);
            acc0 += ev0 * h0.x; acc1 += ev0 * h0.y;
            acc0 += ev1 * h1.x; acc1 += ev1 * h1.y;
            acc0 += ev2 * h2.x; acc1 += ev2 * h2.y;
            acc0 += ev3 * h3.x; acc1 += ev3 * h3.y;
            dsum += (ev0 + ev1) + (ev2 + ev3);
        }
    }
    float inv = 1.f / (dsum + 1e-16f);
    float o0 = acc0 * inv + bias1[2 * l];
    float o1 = acc1 * inv + bias1[2 * l + 1];
    o0 = (o0 > 0.f) ? o0 : expm1f(o0);
    o1 = (o1 > 0.f) ? o1 : expm1f(o1);
    ((float2*)(d_x1 + (size_t)node * 64))[l] = make_float2(o0, o1);
}

// ---------------------------- Layer 2 GEMM -------------------------------
__global__ __launch_bounds__(256) void k_gemm2(
    const float* __restrict__ W2, const float* __restrict__ as2,
    const float* __restrict__ ad2, int n)
{
    __shared__ float4 Ws[64 * 32];
    __shared__ float atts[128], attd[128];
    int t = threadIdx.x, w = t >> 5, l = t & 31;
    const float4* Wv = (const float4*)W2;
    for (int i = t; i < 2048; i += 256) Ws[i] = Wv[i];
    if (t < 128) { atts[t] = as2[t]; attd[t] = ad2[t]; }
    __syncthreads();
    int ntiles = (n + 3) >> 2;
    for (int tile = blockIdx.x * 8 + w; tile < ntiles; tile += gridDim.x * 8) {
        int row0 = tile * 4;
        float xr[4][2];
#pragma unroll
        for (int r = 0; r < 4; r++) {
            const float* xp = d_x1 + (size_t)min(row0 + r, n - 1) * 64;
#pragma unroll
            for (int c = 0; c < 2; c++) xr[r][c] = xp[l + 32 * c];
        }
        float4 acc[4] = {{0,0,0,0},{0,0,0,0},{0,0,0,0},{0,0,0,0}};
#pragma unroll
        for (int c = 0; c < 2; c++) {
#pragma unroll 8
            for (int kk = 0; kk < 32; kk++) {
                float4 wv = Ws[(c * 32 + kk) * 32 + l];
#pragma unroll
                for (int r = 0; r < 4; r++) {
                    float xv = __shfl_sync(0xffffffffu, xr[r][c], kk);
                    acc[r].x += xv * wv.x; acc[r].y += xv * wv.y;
                    acc[r].z += xv * wv.z; acc[r].w += xv * wv.w;
                }
            }
        }
#pragma unroll
        for (int r = 0; r < 4; r++) {
            int row = row0 + r;
            if (row >= n) break;
            ((float4*)(d_h2 + (size_t)row * 128))[l] = acc[r];
            float ps = acc[r].x * atts[4 * l]     + acc[r].y * atts[4 * l + 1]
                     + acc[r].z * atts[4 * l + 2] + acc[r].w * atts[4 * l + 3];
            float pd = acc[r].x * attd[4 * l]     + acc[r].y * attd[4 * l + 1]
                     + acc[r].z * attd[4 * l + 2] + acc[r].w * attd[4 * l + 3];
#pragma unroll
            for (int o = 16; o; o >>= 1) {
                ps += __shfl_xor_sync(0xffffffffu, ps, o);
                pd += __shfl_xor_sync(0xffffffffu, pd, o);
            }
            if (l == 0) { d_as2[row] = ps; d_ad2[row] = pd; }
        }
    }
}

// --------------------------- Layer 2 aggregate ---------------------------
// warp per dst node; lane l owns channels 4l..4l+3; groups of 8 independent
// LDG.128s (MLP 8) to cover L2-hit latency.
__global__ __launch_bounds__(256) void k_agg2(
    const float* __restrict__ bias2, float* __restrict__ out, int n)
{
    int t = threadIdx.x, w = t >> 5, l = t & 31;
    int node = blockIdx.x * 8 + w;
    if (node >= n) return;
    float adv = d_ad2[node];
    int beg = d_off[node], end = d_off[node + 1];
    float c0 = 0.f, c1 = 0.f, c2 = 0.f, c3 = 0.f;
    float dpart = 0.f;
    for (int ch = beg; ch < end; ch += 32) {
        int cnt = end - ch;
        int idx = d_ssrc[min(ch + l, end - 1)];
        float e = 0.f;
        if (l < cnt) {
            float al = __ldg(&d_as2[idx]) + adv;
            al = (al >= 0.f) ? al : 0.2f * al;
            e = __expf(al);
            dpart += e;
        }
#pragma unroll
        for (int g = 0; g < 4; g++) {
            if (g * 8 >= cnt) break;
            int   sj[8];
            float ej[8];
#pragma unroll
            for (int j = 0; j < 8; j++) {
                sj[j] = __shfl_sync(0xffffffffu, idx, g * 8 + j);
                ej[j] = __shfl_sync(0xffffffffu, e,   g * 8 + j);
            }
            float4 hj[8];
#pragma unroll
            for (int j = 0; j < 8; j++)
                hj[j] = ((const float4*)(d_h2 + (size_t)sj[j] * 128))[l];
#pragma unroll
            for (int j = 0; j < 8; j++) {
                c0 += ej[j] * hj[j].x; c1 += ej[j] * hj[j].y;
                c2 += ej[j] * hj[j].z; c3 += ej[j] * hj[j].w;
            }
        }
    }
#pragma unroll
    for (int o = 16; o; o >>= 1) dpart += __shfl_xor_sync(0xffffffffu, dpart, o);
    float inv = 1.f / (dpart + 1e-16f);
    float4 b = ((const float4*)bias2)[l];
    float4 o4 = make_float4(c0 * inv + b.x, c1 * inv + b.y,
                            c2 * inv + b.z, c3 * inv + b.w);
    ((float4*)(out + (size_t)node * 128))[l] = o4;
}

// ------------------------------- launch ----------------------------------
extern "C" void kernel_launch(void* const* d_in, const int* in_sizes, int n_in,
                              void* d_out, int out_size)
{
    const float* x    = (const float*)d_in[0];
    const int*   ei   = (const int*)d_in[1];
    const float* W1   = (const float*)d_in[2];
    const float* asr1 = (const float*)d_in[3];
    const float* ads1 = (const float*)d_in[4];
    const float* b1   = (const float*)d_in[5];
    const float* W2   = (const float*)d_in[6];
    const float* asr2 = (const float*)d_in[7];
    const float* ads2 = (const float*)d_in[8];
    const float* b2   = (const float*)d_in[9];
    float* out = (float*)d_out;

    int N  = in_sizes[0] / 128;
    int E  = in_sizes[1] / 2;
    int vec = ((E & 3) == 0) ? 1 : 0;
    int e4 = (E + 3) / 4;

    k_zero_deg<<<(N + 255) / 256, 256>>>(N);
    k_hist<<<(e4 + 255) / 256, 256>>>(ei, E, vec);
    k_scan<<<1, 1024>>>(N);

    // fused: gemm1 (blocks [0,ntb)) + scatter (blocks [ntb, ntb+sb))
    int ntb = ((N + 3) / 4 + 7) / 8;
    int sb  = (e4 + 255) / 256;
    k_gemm1_scatter<<<ntb + sb, 256>>>(x, W1, asr1, ads1, N, ei, E, vec, ntb);

    k_agg1<<<(N + 7) / 8, 256>>>(b1, N);
    k_gemm2<<<ntb, 256>>>(W2, asr2, ads2, N);
    k_agg2<<<(N + 7) / 8, 256>>>(b2, out, N);
}

// round 7
// speedup vs baseline: 1.1838x; 1.0309x over previous
#include <cuda_runtime.h>
#include <math.h>

#define MAXN 50048
#define MAXE 1650080

// ------------ static device scratch -------------
__device__ float d_h1[MAXN * 64];
__device__ float d_as1[MAXN * 8];
__device__ float d_ad1[MAXN * 8];
__device__ float d_x1[MAXN * 64];
__device__ float d_z[MAXN * 64];     // layer2 aggregated x1 (pre-GEMM)
__device__ float d_as2[MAXN];
__device__ float d_ad2[MAXN];
__device__ float d_wsrc[64];
__device__ float d_wdst[64];
__device__ int   d_deg[MAXN];
__device__ int   d_off[MAXN + 1];
__device__ int   d_cur[MAXN];
__device__ int   d_ssrc[MAXE];

// ------------------- init: zero deg + wsrc/wdst = W2 @ att2 ---------------
__global__ void k_init(int n, const float* __restrict__ W2,
                       const float* __restrict__ as2v, const float* __restrict__ ad2v) {
    int i = blockIdx.x * blockDim.x + threadIdx.x;
    if (i < n) d_deg[i] = 0;
    if (blockIdx.x == 0 && threadIdx.x < 128) {
        int k = threadIdx.x & 63;
        const float* att = (threadIdx.x < 64) ? as2v : ad2v;
        float s = 0.f;
#pragma unroll 16
        for (int c = 0; c < 128; c++) s += W2[k * 128 + c] * att[c];
        if (threadIdx.x < 64) d_wsrc[k] = s;
        else                  d_wdst[k] = s;
    }
}

__global__ void k_hist(const int* __restrict__ ei, int E, int vec) {
    int i = blockIdx.x * blockDim.x + threadIdx.x;
    int e = i * 4;
    if (e >= E) return;
    if (vec && e + 3 < E) {
        int4 d = *(const int4*)(ei + E + e);
        atomicAdd(&d_deg[d.x], 1);
        atomicAdd(&d_deg[d.y], 1);
        atomicAdd(&d_deg[d.z], 1);
        atomicAdd(&d_deg[d.w], 1);
    } else {
        for (int j = e; j < E && j < e + 4; j++)
            atomicAdd(&d_deg[ei[E + j]], 1);
    }
}

// single-block scan; places self loop at slot 0 of each segment
__global__ __launch_bounds__(1024) void k_scan(int n) {
    __shared__ int warpsum[32];
    int t = threadIdx.x, lane = t & 31, wid = t >> 5;
    int ipt = (n + 1023) >> 10;
    int start = t * ipt;
    int endi  = min(start + ipt, n);
    int s = 0;
    for (int i = start; i < endi; i++) s += d_deg[i] + 1;
    int incl = s;
#pragma unroll
    for (int o = 1; o < 32; o <<= 1) {
        int v = __shfl_up_sync(0xffffffffu, incl, o);
        if (lane >= o) incl += v;
    }
    if (lane == 31) warpsum[wid] = incl;
    __syncthreads();
    if (wid == 0) {
        int v = warpsum[lane];
        int wi = v;
#pragma unroll
        for (int o = 1; o < 32; o <<= 1) {
            int u = __shfl_up_sync(0xffffffffu, wi, o);
            if (lane >= o) wi += u;
        }
        warpsum[lane] = wi - v;
    }
    __syncthreads();
    int run = warpsum[wid] + (incl - s);
    for (int i = start; i < endi; i++) {
        int d = d_deg[i];
        d_off[i]  = run;
        d_ssrc[run] = i;
        d_cur[i]  = run + 1;
        run += d + 1;
    }
    if (t == 1023) d_off[n] = run;
}

// ------------- Fused Layer-1 GEMM + scatter (interleaved roles) -----------
// even blocks: gemm (grid-stride, G/2 blocks); odd blocks: scatter
__global__ __launch_bounds__(256) void k_gemm1_scatter(
    const float* __restrict__ x, const float* __restrict__ W1,
    const float* __restrict__ as, const float* __restrict__ ad, int n,
    const int* __restrict__ ei, int E, int vec)
{
    __shared__ float2 Ws[128 * 32];
    __shared__ float atts[64], attd[64];
    int t = threadIdx.x;

    if (blockIdx.x & 1) {
        int i = (blockIdx.x >> 1) * blockDim.x + t;
        int e = i * 4;
        if (e >= E) return;
        if (vec && e + 3 < E) {
            int4 s = *(const int4*)(ei + e);
            int4 d = *(const int4*)(ei + E + e);
            d_ssrc[atomicAdd(&d_cur[d.x], 1)] = s.x;
            d_ssrc[atomicAdd(&d_cur[d.y], 1)] = s.y;
            d_ssrc[atomicAdd(&d_cur[d.z], 1)] = s.z;
            d_ssrc[atomicAdd(&d_cur[d.w], 1)] = s.w;
        } else {
            for (int j = e; j < E && j < e + 4; j++)
                d_ssrc[atomicAdd(&d_cur[ei[E + j]], 1)] = ei[j];
        }
        return;
    }

    int w = t >> 5, l = t & 31;
    int nblk = gridDim.x >> 1;
    int bid  = blockIdx.x >> 1;
    const float2* Wv = (const float2*)W1;
    for (int i = t; i < 4096; i += 256) Ws[i] = Wv[i];
    if (t < 64) { atts[t] = as[t]; attd[t] = ad[t]; }
    __syncthreads();
    int ntiles = (n + 3) >> 2;
    for (int tile = bid * 8 + w; tile < ntiles; tile += nblk * 8) {
        int row0 = tile * 4;
        float xr[4][4];
#pragma unroll
        for (int r = 0; r < 4; r++) {
            const float* xp = x + (size_t)min(row0 + r, n - 1) * 128;
#pragma unroll
            for (int c = 0; c < 4; c++) xr[r][c] = xp[l + 32 * c];
        }
        float2 acc[4] = {{0,0},{0,0},{0,0},{0,0}};
#pragma unroll
        for (int c = 0; c < 4; c++) {
#pragma unroll 8
            for (int kk = 0; kk < 32; kk++) {
                float2 wv = Ws[(c * 32 + kk) * 32 + l];
#pragma unroll
                for (int r = 0; r < 4; r++) {
                    float xv = __shfl_sync(0xffffffffu, xr[r][c], kk);
                    acc[r].x += xv * wv.x;
                    acc[r].y += xv * wv.y;
                }
            }
        }
#pragma unroll
        for (int r = 0; r < 4; r++) {
            int row = row0 + r;
            if (row >= n) break;
            ((float2*)(d_h1 + (size_t)row * 64))[l] = acc[r];
            float ps = acc[r].x * atts[2 * l] + acc[r].y * atts[2 * l + 1];
            float pd = acc[r].x * attd[2 * l] + acc[r].y * attd[2 * l + 1];
            ps += __shfl_xor_sync(0xffffffffu, ps, 1);
            ps += __shfl_xor_sync(0xffffffffu, ps, 2);
            pd += __shfl_xor_sync(0xffffffffu, pd, 1);
            pd += __shfl_xor_sync(0xffffffffu, pd, 2);
            if ((l & 3) == 0) {
                d_as1[row * 8 + (l >> 2)] = ps;
                d_ad1[row * 8 + (l >> 2)] = pd;
            }
        }
    }
}

// --------------------------- Layer 1 aggregate ---------------------------
// warp per dst node; lane l owns x1 channels 2l,2l+1 (head = l>>2).
// Epilogue also computes a_src2/a_dst2 = x1 . (W2 @ att2).
__global__ __launch_bounds__(256) void k_agg1(const float* __restrict__ bias1, int n) {
    int t = threadIdx.x, w = t >> 5, l = t & 31;
    int node = blockIdx.x * 8 + w;
    if (node >= n) return;
    int hl = l >> 2;
    float adv = d_ad1[node * 8 + (l & 7)];
    int beg = d_off[node], end = d_off[node + 1];
    float acc0 = 0.f, acc1 = 0.f, dsum = 0.f;
    for (int ch = beg; ch < end; ch += 32) {
        int cnt = end - ch;
        int idx = d_ssrc[min(ch + l, end - 1)];
        float ec[8];
#pragma unroll
        for (int g = 0; g < 8; g++) {
            int ka = g * 4 + (l >> 3);
            int sA = __shfl_sync(0xffffffffu, idx, g * 4 + (l >> 3));
            float e = 0.f;
            if (ka < cnt) {
                float al = __ldg(&d_as1[sA * 8 + (l & 7)]) + adv;
                al = (al >= 0.f) ? al : 0.2f * al;
                e = __expf(al);
            }
            ec[g] = e;
        }
#pragma unroll
        for (int g8 = 0; g8 < 4; g8++) {
            if (g8 * 8 >= cnt) break;
            int sj[8];
#pragma unroll
            for (int j = 0; j < 8; j++)
                sj[j] = __shfl_sync(0xffffffffu, idx, g8 * 8 + j);
            float2 hj[8];
#pragma unroll
            for (int j = 0; j < 8; j++)
                hj[j] = ((const float2*)(d_h1 + (size_t)sj[j] * 64))[l];
            float ev[8];
#pragma unroll
            for (int j = 0; j < 8; j++)
                ev[j] = __shfl_sync(0xffffffffu, ec[g8 * 2 + (j >> 2)], (j & 3) * 8 + hl);
#pragma unroll
            for (int j = 0; j < 8; j++) {
                acc0 += ev[j] * hj[j].x;
                acc1 += ev[j] * hj[j].y;
                dsum += ev[j];
            }
        }
    }
    float inv = 1.f / (dsum + 1e-16f);
    float o0 = acc0 * inv + bias1[2 * l];
    float o1 = acc1 * inv + bias1[2 * l + 1];
    o0 = (o0 > 0.f) ? o0 : expm1f(o0);
    o1 = (o1 > 0.f) ? o1 : expm1f(o1);
    ((float2*)(d_x1 + (size_t)node * 64))[l] = make_float2(o0, o1);
    // layer-2 logits: a_src2 = x1 . wsrc ; a_dst2 = x1 . wdst
    float ss = o0 * d_wsrc[2 * l] + o1 * d_wsrc[2 * l + 1];
    float sd = o0 * d_wdst[2 * l] + o1 * d_wdst[2 * l + 1];
#pragma unroll
    for (int o = 16; o; o >>= 1) {
        ss += __shfl_xor_sync(0xffffffffu, ss, o);
        sd += __shfl_xor_sync(0xffffffffu, sd, o);
    }
    if (l == 0) { d_as2[node] = ss; d_ad2[node] = sd; }
}

// --------------------------- Layer 2 aggregate ---------------------------
// z[node] = softmax-weighted sum of x1[src] (256B rows); GEMM applied after.
__global__ __launch_bounds__(256) void k_agg2(int n) {
    int t = threadIdx.x, w = t >> 5, l = t & 31;
    int node = blockIdx.x * 8 + w;
    if (node >= n) return;
    float adv = d_ad2[node];
    int beg = d_off[node], end = d_off[node + 1];
    float a0 = 0.f, a1 = 0.f, dpart = 0.f;
    for (int ch = beg; ch < end; ch += 32) {
        int cnt = end - ch;
        int idx = d_ssrc[min(ch + l, end - 1)];
        float e = 0.f;
        if (l < cnt) {
            float al = __ldg(&d_as2[idx]) + adv;
            al = (al >= 0.f) ? al : 0.2f * al;
            e = __expf(al);
            dpart += e;
        }
#pragma unroll
        for (int g8 = 0; g8 < 4; g8++) {
            if (g8 * 8 >= cnt) break;
            int sj[8];
            float ej[8];
#pragma unroll
            for (int j = 0; j < 8; j++) {
                sj[j] = __shfl_sync(0xffffffffu, idx, g8 * 8 + j);
                ej[j] = __shfl_sync(0xffffffffu, e,   g8 * 8 + j);
            }
            float2 hj[8];
#pragma unroll
            for (int j = 0; j < 8; j++)
                hj[j] = ((const float2*)(d_x1 + (size_t)sj[j] * 64))[l];
#pragma unroll
            for (int j = 0; j < 8; j++) {
                a0 += ej[j] * hj[j].x;
                a1 += ej[j] * hj[j].y;
            }
        }
    }
#pragma unroll
    for (int o = 16; o; o >>= 1) dpart += __shfl_xor_sync(0xffffffffu, dpart, o);
    float inv = 1.f / (dpart + 1e-16f);
    ((float2*)(d_z + (size_t)node * 64))[l] = make_float2(a0 * inv, a1 * inv);
}

// ---------------------- Final GEMM: out = z @ W2 + b2 --------------------
__global__ __launch_bounds__(256) void k_gemmF(
    const float* __restrict__ W2, const float* __restrict__ bias2,
    float* __restrict__ out, int n)
{
    __shared__ float4 Ws[64 * 32];
    __shared__ float4 bs[32];
    int t = threadIdx.x, w = t >> 5, l = t & 31;
    const float4* Wv = (const float4*)W2;
    for (int i = t; i < 2048; i += 256) Ws[i] = Wv[i];
    if (t < 32) bs[t] = ((const float4*)bias2)[t];
    __syncthreads();
    int ntiles = (n + 3) >> 2;
    for (int tile = blockIdx.x * 8 + w; tile < ntiles; tile += gridDim.x * 8) {
        int row0 = tile * 4;
        float xr[4][2];
#pragma unroll
        for (int r = 0; r < 4; r++) {
            const float* xp = d_z + (size_t)min(row0 + r, n - 1) * 64;
#pragma unroll
            for (int c = 0; c < 2; c++) xr[r][c] = xp[l + 32 * c];
        }
        float4 acc[4] = {{0,0,0,0},{0,0,0,0},{0,0,0,0},{0,0,0,0}};
#pragma unroll
        for (int c = 0; c < 2; c++) {
#pragma unroll 8
            for (int kk = 0; kk < 32; kk++) {
                float4 wv = Ws[(c * 32 + kk) * 32 + l];
#pragma unroll
                for (int r = 0; r < 4; r++) {
                    float xv = __shfl_sync(0xffffffffu, xr[r][c], kk);
                    acc[r].x += xv * wv.x; acc[r].y += xv * wv.y;
                    acc[r].z += xv * wv.z; acc[r].w += xv * wv.w;
                }
            }
        }
        float4 b = bs[l];
#pragma unroll
        for (int r = 0; r < 4; r++) {
            int row = row0 + r;
            if (row >= n) break;
            float4 o4 = make_float4(acc[r].x + b.x, acc[r].y + b.y,
                                    acc[r].z + b.z, acc[r].w + b.w);
            ((float4*)(out + (size_t)row * 128))[l] = o4;
        }
    }
}

// ------------------------------- launch ----------------------------------
extern "C" void kernel_launch(void* const* d_in, const int* in_sizes, int n_in,
                              void* d_out, int out_size)
{
    const float* x    = (const float*)d_in[0];
    const int*   ei   = (const int*)d_in[1];
    const float* W1   = (const float*)d_in[2];
    const float* asr1 = (const float*)d_in[3];
    const float* ads1 = (const float*)d_in[4];
    const float* b1   = (const float*)d_in[5];
    const float* W2   = (const float*)d_in[6];
    const float* asr2 = (const float*)d_in[7];
    const float* ads2 = (const float*)d_in[8];
    const float* b2   = (const float*)d_in[9];
    float* out = (float*)d_out;

    int N  = in_sizes[0] / 128;
    int E  = in_sizes[1] / 2;
    int vec = ((E & 3) == 0) ? 1 : 0;
    int e4 = (E + 3) / 4;

    k_init<<<(N + 255) / 256, 256>>>(N, W2, asr2, ads2);
    k_hist<<<(e4 + 255) / 256, 256>>>(ei, E, vec);
    k_scan<<<1, 1024>>>(N);

    int ntb = ((N + 3) / 4 + 7) / 8;
    int sb  = (e4 + 255) / 256;
    int G   = 2 * (ntb > sb ? ntb : sb);
    k_gemm1_scatter<<<G, 256>>>(x, W1, asr1, ads1, N, ei, E, vec);

    k_agg1<<<(N + 7) / 8, 256>>>(b1, N);
    k_agg2<<<(N + 7) / 8, 256>>>(N);
    k_gemmF<<<ntb, 256>>>(W2, b2, out, N);
}